// round 2
// baseline (speedup 1.0000x reference)
#include <cuda_runtime.h>
#include <cuda_bf16.h>
#include <cstdint>

// Problem constants (fixed by the reference)
#define N_NODES 100000
#define N_EDGES 1600000
#define D_NODE  128
#define D_EDGE  128
#define D_IN    256
#define HID     256
#define D_OUT   128

// Scratch: scatter-sum accumulator + degree counts (device globals; no allocs)
__device__ __align__(16) float g_sum[(size_t)N_NODES * D_EDGE];
__device__ int g_cnt[N_NODES];

// ---------------------------------------------------------------------------
// Kernel 1: zero scratch
// ---------------------------------------------------------------------------
__global__ void zero_kernel() {
    int i = blockIdx.x * blockDim.x + threadIdx.x;
    const int total = N_NODES * D_EDGE;
    if (i < total) g_sum[i] = 0.0f;
    if (i < N_NODES) g_cnt[i] = 0;
}

// ---------------------------------------------------------------------------
// Kernel 2: degree counts
// ---------------------------------------------------------------------------
__global__ void count_kernel(const int* __restrict__ col, int n_edges) {
    int e = blockIdx.x * blockDim.x + threadIdx.x;
    if (e < n_edges) atomicAdd(&g_cnt[col[e]], 1);
}

// ---------------------------------------------------------------------------
// Kernel 3: scatter-add edge_attr into g_sum.
// One warp covers exactly one edge row (32 lanes x float4 = 128 floats),
// so edge_attr reads are perfectly coalesced and col[] is a broadcast load.
// ---------------------------------------------------------------------------
__global__ void scatter_kernel(const int* __restrict__ col,
                               const float4* __restrict__ edge_attr,
                               int n_edges) {
    long long gid = (long long)blockIdx.x * blockDim.x + threadIdx.x;
    if (gid >= (long long)n_edges * 32) return;
    int e = (int)(gid >> 5);
    int c = (int)(gid & 31);
    int dst = __ldg(col + e);
    float4 v = __ldg(edge_attr + (size_t)e * 32 + c);
    float* p = g_sum + (size_t)dst * D_EDGE + c * 4;
    atomicAdd(p + 0, v.x);
    atomicAdd(p + 1, v.y);
    atomicAdd(p + 2, v.z);
    atomicAdd(p + 3, v.w);
}

// ---------------------------------------------------------------------------
// Kernel 4: fused MLP. One block = 64 nodes. All intermediates in smem.
// Threads: 256 as 16x16; each thread owns a 4x4 microtile per 64-col chunk.
// smem row stride 260 floats -> conflict-free column reads (4*row mod 32).
// ---------------------------------------------------------------------------
#define LDS_STRIDE 260
#define TILE_M 64
#define SMEM_FLOATS (2 * TILE_M * LDS_STRIDE + 16 * 64)

__device__ __forceinline__ void gemm_chunks(
    const float* __restrict__ sIn,   // [64][LDS_STRIDE], K values per row
    const float* __restrict__ W,     // [K][Nout] row-major in gmem
    const float* __restrict__ bias,  // [Nout]
    int K, int Nout,
    float* __restrict__ sOut,        // [64][LDS_STRIDE]
    bool relu, float* __restrict__ sW, int tx, int ty, int tid)
{
    for (int n0 = 0; n0 < Nout; n0 += 64) {
        float acc[4][4] = {};
        const float* aBase0 = sIn + (ty * 4 + 0) * LDS_STRIDE;
        const float* aBase1 = sIn + (ty * 4 + 1) * LDS_STRIDE;
        const float* aBase2 = sIn + (ty * 4 + 2) * LDS_STRIDE;
        const float* aBase3 = sIn + (ty * 4 + 3) * LDS_STRIDE;
        for (int k0 = 0; k0 < K; k0 += 16) {
            // Stage W[k0:k0+16][n0:n0+64] (16x64 fp32 = 4KB) cooperatively
            int kr = tid >> 4;   // 0..15
            int c4 = tid & 15;   // 0..15
            float4 wv = __ldg((const float4*)(W + (size_t)(k0 + kr) * Nout + n0) + c4);
            __syncthreads();                 // previous tile fully consumed
            ((float4*)sW)[tid] = wv;
            __syncthreads();
            #pragma unroll
            for (int kk = 0; kk < 16; kk++) {
                float a0 = aBase0[k0 + kk];
                float a1 = aBase1[k0 + kk];
                float a2 = aBase2[k0 + kk];
                float a3 = aBase3[k0 + kk];
                float4 b = *(const float4*)(sW + kk * 64 + tx * 4);
                acc[0][0] += a0 * b.x; acc[0][1] += a0 * b.y; acc[0][2] += a0 * b.z; acc[0][3] += a0 * b.w;
                acc[1][0] += a1 * b.x; acc[1][1] += a1 * b.y; acc[1][2] += a1 * b.z; acc[1][3] += a1 * b.w;
                acc[2][0] += a2 * b.x; acc[2][1] += a2 * b.y; acc[2][2] += a2 * b.z; acc[2][3] += a2 * b.w;
                acc[3][0] += a3 * b.x; acc[3][1] += a3 * b.y; acc[3][2] += a3 * b.z; acc[3][3] += a3 * b.w;
            }
        }
        // Epilogue: bias (+ReLU), write into sOut chunk
        float4 bv = __ldg((const float4*)(bias + n0) + tx);
        #pragma unroll
        for (int i = 0; i < 4; i++) {
            float v0 = acc[i][0] + bv.x;
            float v1 = acc[i][1] + bv.y;
            float v2 = acc[i][2] + bv.z;
            float v3 = acc[i][3] + bv.w;
            if (relu) {
                v0 = fmaxf(v0, 0.f); v1 = fmaxf(v1, 0.f);
                v2 = fmaxf(v2, 0.f); v3 = fmaxf(v3, 0.f);
            }
            float* p = sOut + (ty * 4 + i) * LDS_STRIDE + n0 + tx * 4;
            p[0] = v0; p[1] = v1; p[2] = v2; p[3] = v3;
        }
    }
}

__global__ void __launch_bounds__(256, 1)
mlp_kernel(const float* __restrict__ x,
           const float* __restrict__ W1, const float* __restrict__ b1,
           const float* __restrict__ W2, const float* __restrict__ b2,
           const float* __restrict__ W3, const float* __restrict__ b3,
           float* __restrict__ out, int n)
{
    extern __shared__ float smem[];
    float* bufA = smem;                          // [64][260]
    float* bufB = smem + TILE_M * LDS_STRIDE;    // [64][260]
    float* sW   = smem + 2 * TILE_M * LDS_STRIDE; // [16][64]

    int tid = threadIdx.x;
    int tx = tid & 15, ty = tid >> 4;
    int m0 = blockIdx.x * TILE_M;

    // ---- Load fused input tile: cols [0,128)=x, [128,256)=g_sum/max(cnt,1)
    for (int i = tid; i < TILE_M * 64; i += 256) {   // 64 float4 per row
        int r = i >> 6;
        int c4 = i & 63;
        int m = m0 + r;
        float4 v = make_float4(0.f, 0.f, 0.f, 0.f);
        if (m < n) {
            if (c4 < 32) {
                v = __ldg((const float4*)(x + (size_t)m * D_NODE) + c4);
            } else {
                v = *((const float4*)(g_sum + (size_t)m * D_EDGE) + (c4 - 32));
                float inv = 1.0f / fmaxf((float)g_cnt[m], 1.0f);
                v.x *= inv; v.y *= inv; v.z *= inv; v.w *= inv;
            }
        }
        *(float4*)(bufA + r * LDS_STRIDE + c4 * 4) = v;
    }
    __syncthreads();

    // ---- Layer 1: bufB = relu(bufA @ W1 + b1)   (K=256, N=256)
    gemm_chunks(bufA, W1, b1, D_IN, HID, bufB, true, sW, tx, ty, tid);
    __syncthreads();
    // ---- Layer 2: bufA = relu(bufB @ W2 + b2)   (K=256, N=256)
    gemm_chunks(bufB, W2, b2, HID, HID, bufA, true, sW, tx, ty, tid);
    __syncthreads();

    // ---- Layer 3: out = bufA @ W3 + b3  (K=256, N=128), direct to gmem
    for (int n0 = 0; n0 < D_OUT; n0 += 64) {
        float acc[4][4] = {};
        const float* aBase0 = bufA + (ty * 4 + 0) * LDS_STRIDE;
        const float* aBase1 = bufA + (ty * 4 + 1) * LDS_STRIDE;
        const float* aBase2 = bufA + (ty * 4 + 2) * LDS_STRIDE;
        const float* aBase3 = bufA + (ty * 4 + 3) * LDS_STRIDE;
        for (int k0 = 0; k0 < HID; k0 += 16) {
            int kr = tid >> 4;
            int c4 = tid & 15;
            float4 wv = __ldg((const float4*)(W3 + (size_t)(k0 + kr) * D_OUT + n0) + c4);
            __syncthreads();
            ((float4*)sW)[tid] = wv;
            __syncthreads();
            #pragma unroll
            for (int kk = 0; kk < 16; kk++) {
                float a0 = aBase0[k0 + kk];
                float a1 = aBase1[k0 + kk];
                float a2 = aBase2[k0 + kk];
                float a3 = aBase3[k0 + kk];
                float4 b = *(const float4*)(sW + kk * 64 + tx * 4);
                acc[0][0] += a0 * b.x; acc[0][1] += a0 * b.y; acc[0][2] += a0 * b.z; acc[0][3] += a0 * b.w;
                acc[1][0] += a1 * b.x; acc[1][1] += a1 * b.y; acc[1][2] += a1 * b.z; acc[1][3] += a1 * b.w;
                acc[2][0] += a2 * b.x; acc[2][1] += a2 * b.y; acc[2][2] += a2 * b.z; acc[2][3] += a2 * b.w;
                acc[3][0] += a3 * b.x; acc[3][1] += a3 * b.y; acc[3][2] += a3 * b.z; acc[3][3] += a3 * b.w;
            }
        }
        float4 bv = __ldg((const float4*)(b3 + n0) + tx);
        #pragma unroll
        for (int i = 0; i < 4; i++) {
            int m = m0 + ty * 4 + i;
            if (m < n) {
                float4 v;
                v.x = acc[i][0] + bv.x;
                v.y = acc[i][1] + bv.y;
                v.z = acc[i][2] + bv.z;
                v.w = acc[i][3] + bv.w;
                *(float4*)(out + (size_t)m * D_OUT + n0 + tx * 4) = v;
            }
        }
    }
}

// ---------------------------------------------------------------------------
// kernel_launch
// Inputs: 0=x [N,128] f32, 1=edge_index [2,E] i32, 2=edge_attr [E,128] f32,
//         3=W1 [256,256], 4=b1 [256], 5=W2 [256,256], 6=b2 [256],
//         7=W3 [256,128], 8=b3 [128].  Output: [N,128] f32.
// ---------------------------------------------------------------------------
extern "C" void kernel_launch(void* const* d_in, const int* in_sizes, int n_in,
                              void* d_out, int out_size) {
    const float* x  = (const float*)d_in[0];
    const int* ei   = (const int*)d_in[1];
    const float* ea = (const float*)d_in[2];
    const float* W1 = (const float*)d_in[3];
    const float* b1 = (const float*)d_in[4];
    const float* W2 = (const float*)d_in[5];
    const float* b2 = (const float*)d_in[6];
    const float* W3 = (const float*)d_in[7];
    const float* b3 = (const float*)d_in[8];
    float* out = (float*)d_out;

    const int n = in_sizes[0] / D_NODE;              // 100000
    const int n_edges = in_sizes[2] / D_EDGE;        // 1600000
    const int* col = ei + n_edges;                   // edge_index[1]

    // 1) zero scratch
    {
        int total = N_NODES * D_EDGE;
        int blocks = (total + 255) / 256;
        zero_kernel<<<blocks, 256>>>();
    }
    // 2) degree counts
    count_kernel<<<(n_edges + 255) / 256, 256>>>(col, n_edges);
    // 3) scatter-add (one warp per edge row)
    {
        long long threads = (long long)n_edges * 32;
        int blocks = (int)((threads + 255) / 256);
        scatter_kernel<<<blocks, 256>>>(col, (const float4*)ea, n_edges);
    }
    // 4) fused MLP
    {
        static int smem_set = 0;
        size_t smem_bytes = SMEM_FLOATS * sizeof(float);   // 137,216 B
        if (!smem_set) {
            cudaFuncSetAttribute(mlp_kernel,
                                 cudaFuncAttributeMaxDynamicSharedMemorySize,
                                 (int)smem_bytes);
            smem_set = 1;
        }
        int blocks = (n + TILE_M - 1) / TILE_M;            // 1563
        mlp_kernel<<<blocks, 256, smem_bytes>>>(x, W1, b1, W2, b2, W3, b3, out, n);
    }
}

// round 4
// speedup vs baseline: 2.5210x; 2.5210x over previous
#include <cuda_runtime.h>
#include <cuda_bf16.h>
#include <cstdint>

// ---------------------------------------------------------------------------
// Problem constants
// ---------------------------------------------------------------------------
#define N_NODES 100000
#define N_EDGES 1600000
#define D_NODE  128
#define D_EDGE  128
#define D_IN    256
#define HID     256
#define D_OUT   128

// ---------------------------------------------------------------------------
// Scratch (device globals; allocations are forbidden)
// ---------------------------------------------------------------------------
__device__ __align__(16) float g_sum[(size_t)N_NODES * D_EDGE];
__device__ int g_cnt[N_NODES];

// Pre-split (bf16 hi/lo) transposed weight blobs, layout:
//   [layer][kchunk(64 k)][n(out-feature)][k_in_chunk(64)]  — rows of 64 bf16
// L1: 4*256*64 = 65536 elems, L2: 65536, L3: 4*128*64 = 32768. Total 163840.
#define WT_L2_OFF 65536
#define WT_L3_OFF 131072
#define WT_ELEMS  163840
__device__ __nv_bfloat16 g_wtA[WT_ELEMS];   // hi
__device__ __nv_bfloat16 g_wtB[WT_ELEMS];   // lo

// ---------------------------------------------------------------------------
// SMEM map (byte offsets inside dynamic smem)
//   act_hi : [256 feat][72 bf16] stride 144B      @ 0      (36864 B)
//   act_lo :                                        @ 36864  (36864 B)
//   wbuf0  : hi [256][72]@+0, lo @+36864           @ 73728  (73728 B)
//   wbuf1  :                                        @ 147456 (73728 B)
// total 221184 B. L3 output scratch (128x68 f32 = 34816 B) overlays act_hi.
// ---------------------------------------------------------------------------
#define ACT_HI_OFF 0
#define ACT_LO_OFF 36864
#define WBUF0_OFF  73728
#define WBUF1_OFF  147456
#define WTERM_OFF  36864          // lo offset inside a wbuf
#define SMEM_BYTES 221184

// ---------------------------------------------------------------------------
// PTX helpers (all arch-portable: sm_80/sm_90 features, valid at compute_103)
// ---------------------------------------------------------------------------
__device__ __forceinline__ uint32_t smem_to_u32(const void* p) {
    uint32_t a;
    asm("{ .reg .u64 t; cvta.to.shared.u64 t, %1; cvt.u32.u64 %0, t; }"
        : "=r"(a) : "l"(p));
    return a;
}

#define LDMX4(r, addr) \
    asm volatile("ldmatrix.sync.aligned.m8n8.x4.shared.b16 {%0,%1,%2,%3}, [%4];" \
        : "=r"((r)[0]), "=r"((r)[1]), "=r"((r)[2]), "=r"((r)[3]) : "r"(addr))

#define LDMX4T(r, addr) \
    asm volatile("ldmatrix.sync.aligned.m8n8.x4.trans.shared.b16 {%0,%1,%2,%3}, [%4];" \
        : "=r"((r)[0]), "=r"((r)[1]), "=r"((r)[2]), "=r"((r)[3]) : "r"(addr))

#define MMA_BF16(d, a, b0v, b1v) \
    asm volatile("mma.sync.aligned.m16n8k16.row.col.f32.bf16.bf16.f32 " \
        "{%0,%1,%2,%3},{%4,%5,%6,%7},{%8,%9},{%0,%1,%2,%3};" \
        : "+f"((d)[0]), "+f"((d)[1]), "+f"((d)[2]), "+f"((d)[3]) \
        : "r"((a)[0]), "r"((a)[1]), "r"((a)[2]), "r"((a)[3]), \
          "r"(b0v), "r"(b1v))

#define CP_ASYNC16(dst, src) \
    asm volatile("cp.async.cg.shared.global [%0], [%1], 16;" \
        :: "r"(dst), "l"(src))

#define CP_COMMIT()  asm volatile("cp.async.commit_group;" ::: "memory")
#define CP_WAIT0()   asm volatile("cp.async.wait_group 0;" ::: "memory")

// fp32 pair -> packed bf16x2 hi + lo (a in low half)
__device__ __forceinline__ void split_pack(float a, float b,
                                           uint32_t& hi, uint32_t& lo) {
    __nv_bfloat16 ah = __float2bfloat16(a);
    __nv_bfloat16 bh = __float2bfloat16(b);
    __nv_bfloat16 al = __float2bfloat16(a - __bfloat162float(ah));
    __nv_bfloat16 bl = __float2bfloat16(b - __bfloat162float(bh));
    hi = ((uint32_t)__bfloat16_as_ushort(bh) << 16) | (uint32_t)__bfloat16_as_ushort(ah);
    lo = ((uint32_t)__bfloat16_as_ushort(bl) << 16) | (uint32_t)__bfloat16_as_ushort(al);
}

// ---------------------------------------------------------------------------
// Kernel 1: zero scratch
// ---------------------------------------------------------------------------
__global__ void zero_kernel() {
    int i = blockIdx.x * blockDim.x + threadIdx.x;
    const int total = N_NODES * D_EDGE;
    if (i < total) g_sum[i] = 0.0f;
    if (i < N_NODES) g_cnt[i] = 0;
}

// ---------------------------------------------------------------------------
// Kernel 2: weight prep — split fp32 -> bf16 hi/lo, transpose to [n][k] blob
// ---------------------------------------------------------------------------
__global__ void prep_kernel(const float* __restrict__ W1,
                            const float* __restrict__ W2,
                            const float* __restrict__ W3) {
    int i = blockIdx.x * blockDim.x + threadIdx.x;
    if (i >= WT_ELEMS) return;
    const float* W;
    int rem, Nl;
    if (i < WT_L2_OFF)      { W = W1; rem = i;             Nl = 256; }
    else if (i < WT_L3_OFF) { W = W2; rem = i - WT_L2_OFF; Nl = 256; }
    else                    { W = W3; rem = i - WT_L3_OFF; Nl = 128; }
    int kc  = rem / (Nl * 64);
    int r2  = rem % (Nl * 64);
    int nIx = r2 >> 6;
    int kin = r2 & 63;
    int k   = kc * 64 + kin;
    float w = __ldg(W + (size_t)k * Nl + nIx);
    __nv_bfloat16 hi = __float2bfloat16(w);
    __nv_bfloat16 lo = __float2bfloat16(w - __bfloat162float(hi));
    g_wtA[i] = hi;
    g_wtB[i] = lo;
}

// ---------------------------------------------------------------------------
// Kernel 3: scatter-add (vector red) + degree count. One warp per edge row.
// ---------------------------------------------------------------------------
__global__ void __launch_bounds__(256)
scatter_kernel(const int* __restrict__ col,
               const float4* __restrict__ edge_attr,
               int n_edges) {
    long long gid = (long long)blockIdx.x * blockDim.x + threadIdx.x;
    if (gid >= (long long)n_edges * 32) return;
    int e = (int)(gid >> 5);
    int c = (int)(gid & 31);
    int dst = __ldg(col + e);
    if (c == 0) atomicAdd(&g_cnt[dst], 1);
    float4 v = __ldg(edge_attr + (size_t)e * 32 + c);
    float* p = g_sum + (size_t)dst * D_EDGE + c * 4;
    asm volatile("red.global.add.v4.f32 [%0], {%1,%2,%3,%4};"
                 :: "l"(p), "f"(v.x), "f"(v.y), "f"(v.z), "f"(v.w)
                 : "memory");
}

// ---------------------------------------------------------------------------
// MLP compute: one chunk (64 K-values) of one layer, NT = n16-tiles per warp
// ---------------------------------------------------------------------------
template<int NT>
__device__ __forceinline__ void compute_chunk(
    float acc[2][8][4], uint32_t wb, uint32_t actHi, uint32_t actLo,
    int nb, int kc, int lane)
{
    const uint32_t aRow = (uint32_t)(lane & 15);
    const uint32_t aKH  = (uint32_t)((lane >> 4) * 16);    // +16B for k cols 8..15
    const uint32_t aBase = wb + (uint32_t)(nb + (int)aRow) * 144u + aKH;
    const uint32_t bK   = (uint32_t)(lane & 15);
    const uint32_t bMH  = (uint32_t)((lane >> 4) * 8);

    #pragma unroll
    for (int ktl = 0; ktl < 4; ktl++) {
        uint32_t ah[NT][4], al[NT][4];
        #pragma unroll
        for (int i = 0; i < NT; i++) {
            LDMX4(ah[i], aBase + (uint32_t)(i * 16) * 144u + (uint32_t)(ktl * 32));
            LDMX4(al[i], aBase + WTERM_OFF + (uint32_t)(i * 16) * 144u + (uint32_t)(ktl * 32));
        }
        uint32_t kByte = (uint32_t)((kc * 4 + ktl) * 16 + (int)bK) * 144u;
        #pragma unroll
        for (int mt = 0; mt < 4; mt++) {
            uint32_t mByte = (uint32_t)(mt * 16 + (int)bMH) * 2u;
            uint32_t bh[4], bl[4];
            LDMX4T(bh, actHi + kByte + mByte);
            LDMX4T(bl, actLo + kByte + mByte);
            #pragma unroll
            for (int i = 0; i < NT; i++) {
                #pragma unroll
                for (int h = 0; h < 2; h++) {
                    MMA_BF16(acc[i][mt * 2 + h], ah[i], bh[2 * h], bh[2 * h + 1]);
                    MMA_BF16(acc[i][mt * 2 + h], ah[i], bl[2 * h], bl[2 * h + 1]);
                    MMA_BF16(acc[i][mt * 2 + h], al[i], bh[2 * h], bh[2 * h + 1]);
                }
            }
        }
    }
}

// Stage weight chunk c (layer = c/4, kc = c%4) into wbuf via cp.async
__device__ __forceinline__ void stage_chunk(int c, uint32_t wb, char* dummy, int tid) {
    int layer = c >> 2, kc = c & 3;
    int Nl = (layer < 2) ? 256 : 128;
    size_t off = (layer == 0 ? 0 : (layer == 1 ? WT_L2_OFF : WT_L3_OFF))
               + (size_t)kc * Nl * 64;
    const char* srcA = (const char*)(g_wtA + off);
    const char* srcB = (const char*)(g_wtB + off);
    int tot = Nl * 8;                            // 16B segments per term
    for (int i = tid; i < tot; i += 256) {
        int row = i >> 3, seg = i & 7;
        uint32_t d = wb + (uint32_t)row * 144u + (uint32_t)seg * 16u;
        CP_ASYNC16(d,              srcA + (size_t)row * 128 + seg * 16);
        CP_ASYNC16(d + WTERM_OFF,  srcB + (size_t)row * 128 + seg * 16);
    }
    CP_COMMIT();
}

// ---------------------------------------------------------------------------
// Kernel 4: fused 3-layer MLP on tensor cores (mma.sync bf16, hi/lo 3-term).
// CTA = 64 nodes, 256 threads (8 warps). Transposed GEMM: D[feat][node].
// ---------------------------------------------------------------------------
__global__ void __launch_bounds__(256, 1)
mlp_kernel(const float* __restrict__ x,
           const float* __restrict__ b1,
           const float* __restrict__ b2,
           const float* __restrict__ b3,
           float* __restrict__ out, int n)
{
    extern __shared__ char sm[];
    const uint32_t sb = smem_to_u32(sm);
    const uint32_t actHi = sb + ACT_HI_OFF;
    const uint32_t actLo = sb + ACT_LO_OFF;
    const uint32_t WB[2] = { sb + WBUF0_OFF, sb + WBUF1_OFF };

    const int tid  = threadIdx.x;
    const int warp = tid >> 5;
    const int lane = tid & 31;
    const int g    = lane >> 2;     // group id (row within tile)
    const int t    = lane & 3;      // thread-in-group (col pair)
    const int m0   = blockIdx.x * 64;

    // ---- prologue: prefetch first weight chunk, fill activations ----------
    stage_chunk(0, WB[0], sm, tid);

    {   // input fill: act[feat][node] = split(concat(x, mean))
        int r = tid >> 2;           // local node 0..63
        int q = tid & 3;            // feature quarter
        int m = m0 + r;
        bool valid = (m < n);
        float inv = 1.0f;
        if (valid) inv = 1.0f / fmaxf((float)__ldg(&g_cnt[m]), 1.0f);
        const float4* xr = (const float4*)(x + (size_t)(valid ? m : 0) * D_NODE);
        const float4* gr = (const float4*)(g_sum + (size_t)(valid ? m : 0) * D_EDGE);
        #pragma unroll
        for (int j = 0; j < 16; j++) {
            int fb = q * 64 + j * 4;
            float4 v = make_float4(0.f, 0.f, 0.f, 0.f);
            if (valid) {
                if (q < 2) v = __ldg(xr + q * 16 + j);
                else {
                    v = __ldg(gr + (q - 2) * 16 + j);
                    v.x *= inv; v.y *= inv; v.z *= inv; v.w *= inv;
                }
            }
            float vals[4] = {v.x, v.y, v.z, v.w};
            #pragma unroll
            for (int e = 0; e < 4; e++) {
                __nv_bfloat16 hi = __float2bfloat16(vals[e]);
                __nv_bfloat16 lo = __float2bfloat16(vals[e] - __bfloat162float(hi));
                size_t o = (size_t)(fb + e) * 144 + (size_t)r * 2;
                *(__nv_bfloat16*)(sm + ACT_HI_OFF + o) = hi;
                *(__nv_bfloat16*)(sm + ACT_LO_OFF + o) = lo;
            }
        }
    }

    float acc[2][8][4];

    // ---- 12 weight chunks: L1 (0-3), L2 (4-7), L3 (8-11) -------------------
    #pragma unroll 1
    for (int c = 0; c < 12; c++) {
        const int layer = c >> 2;
        const int kc    = c & 3;

        if (kc == 0) {
            #pragma unroll
            for (int i = 0; i < 2; i++)
                #pragma unroll
                for (int mt = 0; mt < 8; mt++)
                    #pragma unroll
                    for (int q = 0; q < 4; q++) acc[i][mt][q] = 0.f;
        }

        CP_WAIT0();              // chunk c staged
        __syncthreads();         // + all warps done with the other buffer
        if (c < 11) stage_chunk(c + 1, WB[(c + 1) & 1], sm, tid);

        if (layer < 2) {
            int nb = warp * 32;
            compute_chunk<2>(acc, WB[c & 1], actHi, actLo, nb, kc, lane);
        } else {
            int nb = warp * 16;
            compute_chunk<1>(acc, WB[c & 1], actHi, actLo, nb, kc, lane);
        }

        if (kc == 3 && layer < 2) {
            // layer epilogue: bias + ReLU + split, write back to act buffers
            const float* bias = (layer == 0) ? b1 : b2;
            __syncthreads();     // everyone done READING act for this layer
            int nb = warp * 32;
            #pragma unroll
            for (int i = 0; i < 2; i++) {
                int fb = nb + i * 16;
                float bg  = __ldg(bias + fb + g);
                float bg8 = __ldg(bias + fb + g + 8);
                size_t rowG  = (size_t)(fb + g) * 144;
                size_t rowG8 = (size_t)(fb + g + 8) * 144;
                #pragma unroll
                for (int mt = 0; mt < 8; mt++) {
                    float v0 = fmaxf(acc[i][mt][0] + bg,  0.f);
                    float v1 = fmaxf(acc[i][mt][1] + bg,  0.f);
                    float v2 = fmaxf(acc[i][mt][2] + bg8, 0.f);
                    float v3 = fmaxf(acc[i][mt][3] + bg8, 0.f);
                    uint32_t h01, l01, h23, l23;
                    split_pack(v0, v1, h01, l01);
                    split_pack(v2, v3, h23, l23);
                    size_t mB = (size_t)(mt * 8 + 2 * t) * 2;
                    *(uint32_t*)(sm + ACT_HI_OFF + rowG  + mB) = h01;
                    *(uint32_t*)(sm + ACT_LO_OFF + rowG  + mB) = l01;
                    *(uint32_t*)(sm + ACT_HI_OFF + rowG8 + mB) = h23;
                    *(uint32_t*)(sm + ACT_LO_OFF + rowG8 + mB) = l23;
                }
            }
            __syncthreads();     // writes visible before next layer reads
        }
    }

    // ---- final epilogue: bias, transpose via f32 scratch, coalesced store --
    {
        int nb = warp * 16;
        float bg  = __ldg(b3 + nb + g);
        float bg8 = __ldg(b3 + nb + g + 8);
        __syncthreads();         // all done reading act (scratch overlays it)
        #pragma unroll
        for (int mt = 0; mt < 8; mt++) {
            float2 v01 = make_float2(acc[0][mt][0] + bg,  acc[0][mt][1] + bg);
            float2 v23 = make_float2(acc[0][mt][2] + bg8, acc[0][mt][3] + bg8);
            size_t mB = (size_t)(mt * 8 + 2 * t) * 4;
            *(float2*)(sm + (size_t)(nb + g)     * 272 + mB) = v01;
            *(float2*)(sm + (size_t)(nb + g + 8) * 272 + mB) = v23;
        }
        __syncthreads();
        int mloc = tid >> 2, fgrp = tid & 3;
        int m = m0 + mloc;
        if (m < n) {
            const float* scr = (const float*)sm;
            #pragma unroll
            for (int i = 0; i < 8; i++) {
                int f = fgrp * 32 + i * 4;
                float4 v;
                v.x = scr[(f + 0) * 68 + mloc];
                v.y = scr[(f + 1) * 68 + mloc];
                v.z = scr[(f + 2) * 68 + mloc];
                v.w = scr[(f + 3) * 68 + mloc];
                *(float4*)(out + (size_t)m * D_OUT + f) = v;
            }
        }
    }
}

// ---------------------------------------------------------------------------
// kernel_launch
// Inputs: 0=x [N,128] f32, 1=edge_index [2,E] i32, 2=edge_attr [E,128] f32,
//         3=W1 [256,256], 4=b1, 5=W2 [256,256], 6=b2, 7=W3 [256,128], 8=b3.
// ---------------------------------------------------------------------------
extern "C" void kernel_launch(void* const* d_in, const int* in_sizes, int n_in,
                              void* d_out, int out_size) {
    const float* x  = (const float*)d_in[0];
    const int* ei   = (const int*)d_in[1];
    const float* ea = (const float*)d_in[2];
    const float* W1 = (const float*)d_in[3];
    const float* b1 = (const float*)d_in[4];
    const float* W2 = (const float*)d_in[5];
    const float* b2 = (const float*)d_in[6];
    const float* W3 = (const float*)d_in[7];
    const float* b3 = (const float*)d_in[8];
    float* out = (float*)d_out;

    const int n = in_sizes[0] / D_NODE;              // 100000
    const int n_edges = in_sizes[2] / D_EDGE;        // 1600000
    const int* col = ei + n_edges;                   // edge_index[1]

    // 1) zero scratch
    {
        int total = N_NODES * D_EDGE;
        zero_kernel<<<(total + 255) / 256, 256>>>();
    }
    // 2) weight prep (split + transpose)
    prep_kernel<<<(WT_ELEMS + 255) / 256, 256>>>(W1, W2, W3);
    // 3) scatter-add + counts
    {
        long long threads = (long long)n_edges * 32;
        int blocks = (int)((threads + 255) / 256);
        scatter_kernel<<<blocks, 256>>>(col, (const float4*)ea, n_edges);
    }
    // 4) fused tensor-core MLP
    {
        static int smem_set = 0;
        if (!smem_set) {
            cudaFuncSetAttribute(mlp_kernel,
                                 cudaFuncAttributeMaxDynamicSharedMemorySize,
                                 SMEM_BYTES);
            smem_set = 1;
        }
        int blocks = (n + 63) / 64;                  // 1563
        mlp_kernel<<<blocks, 256, SMEM_BYTES>>>(x, b1, b2, b3, out, n);
    }
}

// round 5
// speedup vs baseline: 3.4695x; 1.3763x over previous
#include <cuda_runtime.h>
#include <cuda_bf16.h>
#include <cstdint>

// ---------------------------------------------------------------------------
// Problem constants
// ---------------------------------------------------------------------------
#define N_NODES 100000
#define N_EDGES 1600000
#define D_NODE  128
#define D_EDGE  128
#define D_IN    256
#define HID     256
#define D_OUT   128

// ---------------------------------------------------------------------------
// Scratch (device globals; allocations are forbidden)
// ---------------------------------------------------------------------------
__device__ __align__(16) float g_sum[(size_t)N_NODES * D_EDGE];
__device__ int g_cnt[N_NODES];

// Weight blob in EXACT mma.sync A-fragment order, bf16 hi/lo terms:
//   b32 index = layerBase + ((kstep*NFT + ft)*2 + term)*128 + lane*4 + reg
// L1: 65536 b32, L2: 65536, L3: 32768  -> total 163840 b32 = 40960 uint4
#define WF_L2_B32 65536
#define WF_L3_B32 131072
#define WF_TOTAL_B32 163840
__device__ __align__(16) uint4 g_wfrag[WF_TOTAL_B32 / 4];

// ---------------------------------------------------------------------------
// SMEM map: activations only (hi + lo), [256 feat][72 bf16] stride 144 B.
// L3 f32 transpose scratch (128 x 68 f32, stride 272 B) overlays act area.
// ---------------------------------------------------------------------------
#define ACT_HI_OFF 0
#define ACT_LO_OFF 36864
#define SMEM_BYTES 73728

// ---------------------------------------------------------------------------
// PTX helpers (arch-portable, valid at compute_103)
// ---------------------------------------------------------------------------
__device__ __forceinline__ uint32_t smem_to_u32(const void* p) {
    uint32_t a;
    asm("{ .reg .u64 t; cvta.to.shared.u64 t, %1; cvt.u32.u64 %0, t; }"
        : "=r"(a) : "l"(p));
    return a;
}

#define LDMX4T(r, addr) \
    asm volatile("ldmatrix.sync.aligned.m8n8.x4.trans.shared.b16 {%0,%1,%2,%3}, [%4];" \
        : "=r"((r)[0]), "=r"((r)[1]), "=r"((r)[2]), "=r"((r)[3]) : "r"(addr))

#define MMA_BF16(d, a, b0v, b1v) \
    asm volatile("mma.sync.aligned.m16n8k16.row.col.f32.bf16.bf16.f32 " \
        "{%0,%1,%2,%3},{%4,%5,%6,%7},{%8,%9},{%0,%1,%2,%3};" \
        : "+f"((d)[0]), "+f"((d)[1]), "+f"((d)[2]), "+f"((d)[3]) \
        : "r"((a)[0]), "r"((a)[1]), "r"((a)[2]), "r"((a)[3]), \
          "r"(b0v), "r"(b1v))

// fp32 pair -> packed bf16x2 hi + lo (a in low half)
__device__ __forceinline__ void split_pack(float a, float b,
                                           uint32_t& hi, uint32_t& lo) {
    __nv_bfloat16 ah = __float2bfloat16(a);
    __nv_bfloat16 bh = __float2bfloat16(b);
    __nv_bfloat16 al = __float2bfloat16(a - __bfloat162float(ah));
    __nv_bfloat16 bl = __float2bfloat16(b - __bfloat162float(bh));
    hi = ((uint32_t)__bfloat16_as_ushort(bh) << 16) | (uint32_t)__bfloat16_as_ushort(ah);
    lo = ((uint32_t)__bfloat16_as_ushort(bl) << 16) | (uint32_t)__bfloat16_as_ushort(al);
}

// ---------------------------------------------------------------------------
// Kernel 1: zero scratch
// ---------------------------------------------------------------------------
__global__ void zero_kernel() {
    int i = blockIdx.x * blockDim.x + threadIdx.x;
    const int total = N_NODES * D_EDGE;
    if (i < total) g_sum[i] = 0.0f;
    if (i < N_NODES) g_cnt[i] = 0;
}

// ---------------------------------------------------------------------------
// Kernel 2: weight prep — write bf16 hi/lo fragments in mma A-operand order.
// reg mapping (m16n8k16 A): reg0=(r, 2t..2t+1), reg1=(r+8, 2t..2t+1),
//                           reg2=(r, 2t+8..9),  reg3=(r+8, 2t+8..9)
// ---------------------------------------------------------------------------
__global__ void prep_kernel(const float* __restrict__ W1,
                            const float* __restrict__ W2,
                            const float* __restrict__ W3) {
    int i = blockIdx.x * blockDim.x + threadIdx.x;
    if (i >= WF_TOTAL_B32) return;
    uint32_t* blob = (uint32_t*)g_wfrag;
    const float* W; int idx, Nl, NFT;
    if (i < WF_L2_B32)      { W = W1; idx = i;             Nl = 256; NFT = 16; }
    else if (i < WF_L3_B32) { W = W2; idx = i - WF_L2_B32; Nl = 256; NFT = 16; }
    else                    { W = W3; idx = i - WF_L3_B32; Nl = 128; NFT = 8;  }
    int reg   = idx & 3;
    int lane  = (idx >> 2) & 31;
    int term  = (idx >> 7) & 1;
    int ft    = (idx >> 8) % NFT;
    int kstep = (idx >> 8) / NFT;
    int r = lane >> 2, t = lane & 3;
    int m = ft * 16 + r + (reg & 1) * 8;             // output feature (A row)
    int k = kstep * 16 + t * 2 + (reg >> 1) * 8;     // fan-in (A col)
    float w0 = __ldg(W + (size_t)k * Nl + m);
    float w1 = __ldg(W + (size_t)(k + 1) * Nl + m);
    uint32_t hi, lo;
    split_pack(w0, w1, hi, lo);
    blob[i] = term ? lo : hi;
}

// ---------------------------------------------------------------------------
// Kernel 3: scatter-add (red.v4) + degree count. One warp per edge row.
// ---------------------------------------------------------------------------
__global__ void __launch_bounds__(256)
scatter_kernel(const int* __restrict__ col,
               const float4* __restrict__ edge_attr,
               int n_edges) {
    long long gid = (long long)blockIdx.x * blockDim.x + threadIdx.x;
    if (gid >= (long long)n_edges * 32) return;
    int e = (int)(gid >> 5);
    int c = (int)(gid & 31);
    int dst = __ldg(col + e);
    if (c == 0) atomicAdd(&g_cnt[dst], 1);
    float4 v = __ldg(edge_attr + (size_t)e * 32 + c);
    float* p = g_sum + (size_t)dst * D_EDGE + c * 4;
    asm volatile("red.global.add.v4.f32 [%0], {%1,%2,%3,%4};"
                 :: "l"(p), "f"(v.x), "f"(v.y), "f"(v.z), "f"(v.w)
                 : "memory");
}

// ---------------------------------------------------------------------------
// MLP compute: one 64-K chunk. A (weights) via direct LDG.128 fragments,
// B (activations) via ldmatrix.trans from smem. 3-term split-bf16.
// ---------------------------------------------------------------------------
template<int NT>
__device__ __forceinline__ void compute_chunk(
    float acc[2][8][4],
    const uint4* __restrict__ wf,    // layer base (uint4 units)
    int ftBase, int NFT, int kc,
    uint32_t actHi, uint32_t actLo, int lane)
{
    const uint32_t bK  = (uint32_t)(lane & 15);
    const uint32_t bMH = (uint32_t)((lane >> 4) * 8);
    #pragma unroll
    for (int ktl = 0; ktl < 4; ktl++) {
        const int kstep = kc * 4 + ktl;
        uint32_t ah[NT][4], al[NT][4];
        #pragma unroll
        for (int i = 0; i < NT; i++) {
            const uint4* p = wf + (size_t)((kstep * NFT + ftBase + i) * 2) * 32 + lane;
            uint4 h = __ldg(p);
            uint4 l = __ldg(p + 32);
            ah[i][0] = h.x; ah[i][1] = h.y; ah[i][2] = h.z; ah[i][3] = h.w;
            al[i][0] = l.x; al[i][1] = l.y; al[i][2] = l.z; al[i][3] = l.w;
        }
        const uint32_t kByte = (uint32_t)(kstep * 16 + (int)bK) * 144u;
        #pragma unroll
        for (int mt = 0; mt < 4; mt++) {
            const uint32_t mByte = (uint32_t)(mt * 16 + (int)bMH) * 2u;
            uint32_t bh[4], bl[4];
            LDMX4T(bh, actHi + kByte + mByte);
            LDMX4T(bl, actLo + kByte + mByte);
            #pragma unroll
            for (int i = 0; i < NT; i++) {
                #pragma unroll
                for (int h = 0; h < 2; h++) {
                    MMA_BF16(acc[i][mt * 2 + h], ah[i], bh[2 * h], bh[2 * h + 1]);
                    MMA_BF16(acc[i][mt * 2 + h], ah[i], bl[2 * h], bl[2 * h + 1]);
                    MMA_BF16(acc[i][mt * 2 + h], al[i], bh[2 * h], bh[2 * h + 1]);
                }
            }
        }
    }
}

// ---------------------------------------------------------------------------
// Kernel 4: fused 3-layer MLP. CTA = 64 nodes, 256 threads, 2 CTAs/SM.
// ---------------------------------------------------------------------------
__global__ void __launch_bounds__(256, 2)
mlp_kernel(const float* __restrict__ x,
           const float* __restrict__ b1,
           const float* __restrict__ b2,
           const float* __restrict__ b3,
           float* __restrict__ out, int n)
{
    extern __shared__ char sm[];
    const uint32_t sb    = smem_to_u32(sm);
    const uint32_t actHi = sb + ACT_HI_OFF;
    const uint32_t actLo = sb + ACT_LO_OFF;

    const int tid  = threadIdx.x;
    const int warp = tid >> 5;
    const int lane = tid & 31;
    const int g    = lane >> 2;
    const int t    = lane & 3;
    const int m0   = blockIdx.x * 64;

    // ---- input fill: act[feat][node] = split(concat(x, mean)) --------------
    {
        int r = tid >> 2;           // local node 0..63
        int q = tid & 3;            // feature quarter
        int m = m0 + r;
        bool valid = (m < n);
        float inv = 1.0f;
        if (valid) inv = 1.0f / fmaxf((float)__ldg(&g_cnt[m]), 1.0f);
        const float4* xr = (const float4*)(x + (size_t)(valid ? m : 0) * D_NODE);
        const float4* gr = (const float4*)(g_sum + (size_t)(valid ? m : 0) * D_EDGE);
        #pragma unroll
        for (int j = 0; j < 16; j++) {
            int fb = q * 64 + j * 4;
            float4 v = make_float4(0.f, 0.f, 0.f, 0.f);
            if (valid) {
                if (q < 2) v = __ldg(xr + q * 16 + j);
                else {
                    v = __ldg(gr + (q - 2) * 16 + j);
                    v.x *= inv; v.y *= inv; v.z *= inv; v.w *= inv;
                }
            }
            float vals[4] = {v.x, v.y, v.z, v.w};
            #pragma unroll
            for (int e = 0; e < 4; e++) {
                __nv_bfloat16 hi = __float2bfloat16(vals[e]);
                __nv_bfloat16 lo = __float2bfloat16(vals[e] - __bfloat162float(hi));
                size_t o = (size_t)(fb + e) * 144 + (size_t)r * 2;
                *(__nv_bfloat16*)(sm + ACT_HI_OFF + o) = hi;
                *(__nv_bfloat16*)(sm + ACT_LO_OFF + o) = lo;
            }
        }
    }
    __syncthreads();

    float acc[2][8][4];

    // ---- Layers 1 & 2 (K=256, N=256) ---------------------------------------
    #pragma unroll 1
    for (int L = 0; L < 2; L++) {
        const uint4* wf = g_wfrag + (L == 0 ? 0 : WF_L2_B32 / 4);
        #pragma unroll
        for (int i = 0; i < 2; i++)
            #pragma unroll
            for (int mt = 0; mt < 8; mt++)
                #pragma unroll
                for (int q = 0; q < 4; q++) acc[i][mt][q] = 0.f;

        #pragma unroll
        for (int kc = 0; kc < 4; kc++)
            compute_chunk<2>(acc, wf, warp * 2, 16, kc, actHi, actLo, lane);

        __syncthreads();     // all warps done READING act for this layer

        // epilogue: bias + ReLU + split, write back to act buffers
        const float* bias = (L == 0) ? b1 : b2;
        const int nb = warp * 32;
        #pragma unroll
        for (int i = 0; i < 2; i++) {
            int fb = nb + i * 16;
            float bg  = __ldg(bias + fb + g);
            float bg8 = __ldg(bias + fb + g + 8);
            size_t rowG  = (size_t)(fb + g) * 144;
            size_t rowG8 = (size_t)(fb + g + 8) * 144;
            #pragma unroll
            for (int mt = 0; mt < 8; mt++) {
                float v0 = fmaxf(acc[i][mt][0] + bg,  0.f);
                float v1 = fmaxf(acc[i][mt][1] + bg,  0.f);
                float v2 = fmaxf(acc[i][mt][2] + bg8, 0.f);
                float v3 = fmaxf(acc[i][mt][3] + bg8, 0.f);
                uint32_t h01, l01, h23, l23;
                split_pack(v0, v1, h01, l01);
                split_pack(v2, v3, h23, l23);
                size_t mB = (size_t)(mt * 8 + 2 * t) * 2;
                *(uint32_t*)(sm + ACT_HI_OFF + rowG  + mB) = h01;
                *(uint32_t*)(sm + ACT_LO_OFF + rowG  + mB) = l01;
                *(uint32_t*)(sm + ACT_HI_OFF + rowG8 + mB) = h23;
                *(uint32_t*)(sm + ACT_LO_OFF + rowG8 + mB) = l23;
            }
        }
        __syncthreads();     // writes visible before next layer reads
    }

    // ---- Layer 3 (K=256, N=128) ---------------------------------------------
    #pragma unroll
    for (int mt = 0; mt < 8; mt++)
        #pragma unroll
        for (int q = 0; q < 4; q++) acc[0][mt][q] = 0.f;

    #pragma unroll
    for (int kc = 0; kc < 4; kc++)
        compute_chunk<1>(acc, g_wfrag + WF_L3_B32 / 4, warp, 8, kc,
                         actHi, actLo, lane);

    // ---- final epilogue: bias, transpose via f32 scratch, coalesced store ---
    {
        const int nb = warp * 16;
        float bg  = __ldg(b3 + nb + g);
        float bg8 = __ldg(b3 + nb + g + 8);
        __syncthreads();     // all done reading act (scratch overlays it)
        #pragma unroll
        for (int mt = 0; mt < 8; mt++) {
            float2 v01 = make_float2(acc[0][mt][0] + bg,  acc[0][mt][1] + bg);
            float2 v23 = make_float2(acc[0][mt][2] + bg8, acc[0][mt][3] + bg8);
            size_t mB = (size_t)(mt * 8 + 2 * t) * 4;
            *(float2*)(sm + (size_t)(nb + g)     * 272 + mB) = v01;
            *(float2*)(sm + (size_t)(nb + g + 8) * 272 + mB) = v23;
        }
        __syncthreads();
        int mloc = tid >> 2, fgrp = tid & 3;
        int m = m0 + mloc;
        if (m < n) {
            const float* scr = (const float*)sm;
            #pragma unroll
            for (int i = 0; i < 8; i++) {
                int f = fgrp * 32 + i * 4;
                float4 v;
                v.x = scr[(f + 0) * 68 + mloc];
                v.y = scr[(f + 1) * 68 + mloc];
                v.z = scr[(f + 2) * 68 + mloc];
                v.w = scr[(f + 3) * 68 + mloc];
                *(float4*)(out + (size_t)m * D_OUT + f) = v;
            }
        }
    }
}

// ---------------------------------------------------------------------------
// kernel_launch
// Inputs: 0=x [N,128] f32, 1=edge_index [2,E] i32, 2=edge_attr [E,128] f32,
//         3=W1 [256,256], 4=b1, 5=W2 [256,256], 6=b2, 7=W3 [256,128], 8=b3.
// ---------------------------------------------------------------------------
extern "C" void kernel_launch(void* const* d_in, const int* in_sizes, int n_in,
                              void* d_out, int out_size) {
    const float* x  = (const float*)d_in[0];
    const int* ei   = (const int*)d_in[1];
    const float* ea = (const float*)d_in[2];
    const float* W1 = (const float*)d_in[3];
    const float* b1 = (const float*)d_in[4];
    const float* W2 = (const float*)d_in[5];
    const float* b2 = (const float*)d_in[6];
    const float* W3 = (const float*)d_in[7];
    const float* b3 = (const float*)d_in[8];
    float* out = (float*)d_out;

    const int n = in_sizes[0] / D_NODE;              // 100000
    const int n_edges = in_sizes[2] / D_EDGE;        // 1600000
    const int* col = ei + n_edges;                   // edge_index[1]

    // 1) zero scratch
    {
        int total = N_NODES * D_EDGE;
        zero_kernel<<<(total + 255) / 256, 256>>>();
    }
    // 2) weight prep (fragment-order split)
    prep_kernel<<<(WF_TOTAL_B32 + 255) / 256, 256>>>(W1, W2, W3);
    // 3) scatter-add + counts
    {
        long long threads = (long long)n_edges * 32;
        int blocks = (int)((threads + 255) / 256);
        scatter_kernel<<<blocks, 256>>>(col, (const float4*)ea, n_edges);
    }
    // 4) fused tensor-core MLP
    {
        static int smem_set = 0;
        if (!smem_set) {
            cudaFuncSetAttribute(mlp_kernel,
                                 cudaFuncAttributeMaxDynamicSharedMemorySize,
                                 SMEM_BYTES);
            smem_set = 1;
        }
        int blocks = (n + 63) / 64;                  // 1563
        mlp_kernel<<<blocks, 256, SMEM_BYTES>>>(x, b1, b2, b3, out, n);
    }
}